// round 3
// baseline (speedup 1.0000x reference)
#include <cuda_runtime.h>
#include <cuda_bf16.h>

#define IMG_H 512
#define IMG_W 512
#define BAND 64
#define NBANDS 8           // 512 / BAND
#define NIMG 96            // 32 batch * 3 channels
#define ROWV4 128          // 512 / 4 float4 per row
#define NT 128
#define XSTR 132           // float4 stride per exchange row (2 pad + 128 + 2 pad)
#define NPIX 25165824.0f   // 32*3*512*512

__device__ float g_partial[NBANDS * NIMG];

__device__ __forceinline__ void horiz11(const float4* q4, int t, float H[4]) {
    // own cols 4t..4t+3 are stored at float4 index (2+t); pads at 0,1,130,131 are zero.
    float4 a = q4[t];         // cols 4t-8 .. 4t-5
    float4 b = q4[t + 1];     // cols 4t-4 .. 4t-1
    float4 c = q4[t + 2];     // cols 4t   .. 4t+3
    float4 d = q4[t + 3];     // cols 4t+4 .. 4t+7
    float  e = ((const float*)q4)[(t + 4) * 4];   // col 4t+8
    float h0 = a.w + b.x + b.y + b.z + b.w
             + c.x + c.y + c.z + c.w + d.x + d.y;     // cols 4t-5..4t+5
    float h1 = h0 - a.w + d.z;                        // cols 4t-4..4t+6
    float h2 = h1 - b.x + d.w;                        // cols 4t-3..4t+7
    float h3 = h2 - b.y + e;                          // cols 4t-2..4t+8
    H[0] = h0; H[1] = h1; H[2] = h2; H[3] = h3;
}

__global__ void __launch_bounds__(NT, 6) ssim_band_kernel(
    const float* __restrict__ pred, const float* __restrict__ targ)
{
    __shared__ float4 xch[5 * XSTR];   // 10560 B: 5 quantities, padded rows
    __shared__ float  red[NT];

    const int t   = threadIdx.x;
    const int img = blockIdx.y;
    const int r0  = blockIdx.x * BAND;

    const float4* __restrict__ P  = (const float4*)pred + (size_t)img * (IMG_H * ROWV4);
    const float4* __restrict__ T4 = (const float4*)targ + (size_t)img * (IMG_H * ROWV4);

    // Zero the halo pads (cols -8..-1 and 512..519) for all 5 quantities.
    if (t < 20) {
        int q  = t >> 2, pi = t & 3;
        int ix = q * XSTR + ((pi < 2) ? pi : 128 + pi);
        xch[ix] = make_float4(0.f, 0.f, 0.f, 0.f);
    }

    float vp[4]  = {0,0,0,0};
    float vt[4]  = {0,0,0,0};
    float vpp[4] = {0,0,0,0};
    float vtt[4] = {0,0,0,0};
    float vpt[4] = {0,0,0,0};
    float acc = 0.f;

    const float K1 = 1.4641f;    // 0.01^2 * 121^2
    const float K2 = 13.1769f;   // 0.03^2 * 121^2

    #pragma unroll 1
    for (int s = 0; s < BAND + 10; ++s) {
        const int iy  = r0 - 5 + s;   // row entering the vertical window
        const int iy2 = iy - 11;      // row leaving the vertical window

        float4 p4  = make_float4(0.f,0.f,0.f,0.f);
        float4 t4  = make_float4(0.f,0.f,0.f,0.f);
        float4 po4 = make_float4(0.f,0.f,0.f,0.f);
        float4 to4 = make_float4(0.f,0.f,0.f,0.f);
        if ((unsigned)iy < IMG_H) {
            p4 = P[iy * ROWV4 + t];
            t4 = T4[iy * ROWV4 + t];
        }
        // Only subtract rows that were actually added: accumulation starts at
        // iy = r0-5 (s=0), so the leaving row is valid only when s >= 11.
        if (s >= 11 && (unsigned)iy2 < IMG_H) {
            po4 = P[iy2 * ROWV4 + t];   // L1/L2 hit: read 11 rows ago
            to4 = T4[iy2 * ROWV4 + t];
        }

        const float pn[4] = {p4.x,  p4.y,  p4.z,  p4.w};
        const float tn[4] = {t4.x,  t4.y,  t4.z,  t4.w};
        const float po[4] = {po4.x, po4.y, po4.z, po4.w};
        const float to[4] = {to4.x, to4.y, to4.z, to4.w};

        #pragma unroll
        for (int k = 0; k < 4; ++k) {
            vp[k]  += pn[k] - po[k];
            vt[k]  += tn[k] - to[k];
            vpp[k]  = fmaf(pn[k], pn[k], vpp[k]);
            vpp[k]  = fmaf(-po[k], po[k], vpp[k]);
            vtt[k]  = fmaf(tn[k], tn[k], vtt[k]);
            vtt[k]  = fmaf(-to[k], to[k], vtt[k]);
            vpt[k]  = fmaf(pn[k], tn[k], vpt[k]);
            vpt[k]  = fmaf(-po[k], to[k], vpt[k]);
        }

        if (s >= 10) {
            __syncthreads();   // WAR: previous step's reads (and pad init) done
            xch[0 * XSTR + 2 + t] = make_float4(vp[0],  vp[1],  vp[2],  vp[3]);
            xch[1 * XSTR + 2 + t] = make_float4(vt[0],  vt[1],  vt[2],  vt[3]);
            xch[2 * XSTR + 2 + t] = make_float4(vpp[0], vpp[1], vpp[2], vpp[3]);
            xch[3 * XSTR + 2 + t] = make_float4(vtt[0], vtt[1], vtt[2], vtt[3]);
            xch[4 * XSTR + 2 + t] = make_float4(vpt[0], vpt[1], vpt[2], vpt[3]);
            __syncthreads();

            float Hp[4], Ht[4], Hpp[4], Htt[4], Hpt[4];
            horiz11(&xch[0 * XSTR], t, Hp);
            horiz11(&xch[1 * XSTR], t, Ht);
            horiz11(&xch[2 * XSTR], t, Hpp);
            horiz11(&xch[3 * XSTR], t, Htt);
            horiz11(&xch[4 * XSTR], t, Hpt);

            #pragma unroll
            for (int k = 0; k < 4; ++k) {
                // SSIM in sum space: all mu/sigma normalizations fold into 121^2 factors.
                float Sp = Hp[k], St = Ht[k];
                float pq  = Sp * St;
                float A   = fmaf(2.f, pq, K1);                       // 2*Sp*St + C1*121^2
                float spq = fmaf(Sp, Sp, St * St);                   // Sp^2 + St^2
                float Cc  = spq + K1;
                float B   = fmaf(242.f, Hpt[k], fmaf(-2.f, pq, K2)); // 2*(121*Spt - Sp*St) + C2*121^2
                float D   = fmaf(121.f, Hpp[k] + Htt[k], K2 - spq);  // 121*(Spp+Stt) - (Sp^2+St^2) + C2*121^2
                acc += __fdividef(A * B, Cc * D);
            }
        }
    }

    // Deterministic block reduction
    red[t] = acc;
    __syncthreads();
    #pragma unroll
    for (int off = NT / 2; off > 0; off >>= 1) {
        if (t < off) red[t] += red[t + off];
        __syncthreads();
    }
    if (t == 0) g_partial[blockIdx.y * NBANDS + blockIdx.x] = red[0];
}

__global__ void __launch_bounds__(256) ssim_final_kernel(float* __restrict__ out)
{
    __shared__ float red[256];
    int t = threadIdx.x;
    float s = g_partial[t] + g_partial[t + 256] + g_partial[t + 512];
    red[t] = s;
    __syncthreads();
    #pragma unroll
    for (int off = 128; off > 0; off >>= 1) {
        if (t < off) red[t] += red[t + off];
        __syncthreads();
    }
    if (t == 0) out[0] = 1.0f - red[0] / NPIX;
}

extern "C" void kernel_launch(void* const* d_in, const int* in_sizes, int n_in,
                              void* d_out, int out_size)
{
    const float* pred = (const float*)d_in[0];
    const float* targ = (const float*)d_in[1];
    dim3 grid(NBANDS, NIMG);
    ssim_band_kernel<<<grid, NT>>>(pred, targ);
    ssim_final_kernel<<<1, 256>>>((float*)d_out);
}

// round 4
// speedup vs baseline: 1.2068x; 1.2068x over previous
#include <cuda_runtime.h>
#include <cuda_bf16.h>

#define IMG_H 512
#define IMG_W 512
#define NBANDS 6
#define BANDH 86           // 5*86 + 82 = 512
#define NIMG 96            // 32 batch * 3 channels
#define ROWV4 128          // 512 / 4 float4 per row
#define NT 128
#define XSTR 132           // float4 stride per exchange row (2 pad + 128 + 2 pad)
#define NPIX 25165824.0f   // 32*3*512*512

__device__ float g_partial[NBANDS * NIMG];

// Horizontal 11-tap sliding sum for 4 owned columns. Own values (cols 4t..4t+3)
// come from registers c0..c3; halo from the padded smem row.
__device__ __forceinline__ void horiz11r(const float* F, int t,
                                         float c0, float c1, float c2, float c3,
                                         float H[4]) {
    float  aw = F[4 * t + 3];                       // col 4t-5
    float4 b  = ((const float4*)F)[t + 1];          // cols 4t-4 .. 4t-1
    float4 d  = ((const float4*)F)[t + 3];          // cols 4t+4 .. 4t+7
    float  e  = F[4 * t + 16];                      // col 4t+8
    float h0 = aw + b.x + b.y + b.z + b.w
             + c0 + c1 + c2 + c3 + d.x + d.y;       // cols 4t-5..4t+5
    float h1 = h0 - aw  + d.z;                      // cols 4t-4..4t+6
    float h2 = h1 - b.x + d.w;                      // cols 4t-3..4t+7
    float h3 = h2 - b.y + e;                        // cols 4t-2..4t+8
    H[0] = h0; H[1] = h1; H[2] = h2; H[3] = h3;
}

__global__ void __launch_bounds__(NT, 4) ssim_band_kernel(
    const float* __restrict__ pred, const float* __restrict__ targ)
{
    __shared__ float4 xch[2][5 * XSTR];   // double-buffered exchange rows (21120 B)
    __shared__ float  red[NT];

    const int t    = threadIdx.x;
    const int img  = blockIdx.y;
    const int band = blockIdx.x;
    const int r0   = band * BANDH;
    const int h    = (band < NBANDS - 1) ? BANDH : (IMG_H - (NBANDS - 1) * BANDH);

    const float4* __restrict__ P  = (const float4*)pred + (size_t)img * (IMG_H * ROWV4);
    const float4* __restrict__ T4 = (const float4*)targ + (size_t)img * (IMG_H * ROWV4);

    // Zero halo pads (float4 idx 0,1,130,131) for all 5 quantities, both buffers.
    // Visibility to readers is ordered by the first __syncthreads (at s=10).
    if (t < 40) {
        int buf = t >> 5 ? 1 : 0;      // t<20 -> buf0 pads... (use t&0x1f over 2 halves)
        int u   = t % 20;
        int q   = u >> 2, pi = u & 3;
        int ix  = q * XSTR + ((pi < 2) ? pi : 128 + pi);
        xch[(t < 20) ? 0 : 1][ix] = make_float4(0.f, 0.f, 0.f, 0.f);
        (void)buf;
    }

    float vp[4]  = {0,0,0,0};
    float vt[4]  = {0,0,0,0};
    float vpp[4] = {0,0,0,0};
    float vtt[4] = {0,0,0,0};
    float vpt[4] = {0,0,0,0};
    float acc = 0.f;

    const float K1 = 1.4641f;    // 0.01^2 * 121^2
    const float K2 = 13.1769f;   // 0.03^2 * 121^2
    const int steps = h + 10;

    #pragma unroll 1
    for (int s = 0; s < steps; ++s) {
        const int iy  = r0 - 5 + s;   // row entering the vertical window
        const int iy2 = iy - 11;      // row leaving the vertical window

        float4 p4  = make_float4(0.f,0.f,0.f,0.f);
        float4 t4  = make_float4(0.f,0.f,0.f,0.f);
        float4 po4 = make_float4(0.f,0.f,0.f,0.f);
        float4 to4 = make_float4(0.f,0.f,0.f,0.f);
        if ((unsigned)iy < IMG_H) {
            p4 = P[iy * ROWV4 + t];
            t4 = T4[iy * ROWV4 + t];
        }
        // Only subtract rows that were actually added (accumulation starts at r0-5).
        if (s >= 11 && (unsigned)iy2 < IMG_H) {
            po4 = P[iy2 * ROWV4 + t];   // L2-resident: read 11 rows ago
            to4 = T4[iy2 * ROWV4 + t];
        }

        const float pn[4] = {p4.x,  p4.y,  p4.z,  p4.w};
        const float tn[4] = {t4.x,  t4.y,  t4.z,  t4.w};
        const float po[4] = {po4.x, po4.y, po4.z, po4.w};
        const float to[4] = {to4.x, to4.y, to4.z, to4.w};

        #pragma unroll
        for (int k = 0; k < 4; ++k) {
            vp[k]  += pn[k] - po[k];
            vt[k]  += tn[k] - to[k];
            vpp[k]  = fmaf(pn[k], pn[k], vpp[k]);
            vpp[k]  = fmaf(-po[k], po[k], vpp[k]);
            vtt[k]  = fmaf(tn[k], tn[k], vtt[k]);
            vtt[k]  = fmaf(-to[k], to[k], vtt[k]);
            vpt[k]  = fmaf(pn[k], tn[k], vpt[k]);
            vpt[k]  = fmaf(-po[k], to[k], vpt[k]);
        }

        if (s >= 10) {
            float4* buf = xch[s & 1];
            buf[0 * XSTR + 2 + t] = make_float4(vp[0],  vp[1],  vp[2],  vp[3]);
            buf[1 * XSTR + 2 + t] = make_float4(vt[0],  vt[1],  vt[2],  vt[3]);
            buf[2 * XSTR + 2 + t] = make_float4(vpp[0], vpp[1], vpp[2], vpp[3]);
            buf[3 * XSTR + 2 + t] = make_float4(vtt[0], vtt[1], vtt[2], vtt[3]);
            buf[4 * XSTR + 2 + t] = make_float4(vpt[0], vpt[1], vpt[2], vpt[3]);
            __syncthreads();   // single barrier; WAR safe via double buffering

            float Hp[4], Ht[4], Hpp[4], Htt[4], Hpt[4];
            horiz11r((const float*)(buf + 0 * XSTR), t, vp[0],  vp[1],  vp[2],  vp[3],  Hp);
            horiz11r((const float*)(buf + 1 * XSTR), t, vt[0],  vt[1],  vt[2],  vt[3],  Ht);
            horiz11r((const float*)(buf + 2 * XSTR), t, vpp[0], vpp[1], vpp[2], vpp[3], Hpp);
            horiz11r((const float*)(buf + 3 * XSTR), t, vtt[0], vtt[1], vtt[2], vtt[3], Htt);
            horiz11r((const float*)(buf + 4 * XSTR), t, vpt[0], vpt[1], vpt[2], vpt[3], Hpt);

            #pragma unroll
            for (int k = 0; k < 4; ++k) {
                // SSIM in sum space: mu/sigma normalizations fold into 121^2 factors.
                float Sp = Hp[k], St = Ht[k];
                float pq  = Sp * St;
                float A   = fmaf(2.f, pq, K1);                       // 2*Sp*St + C1*121^2
                float spq = fmaf(Sp, Sp, St * St);                   // Sp^2 + St^2
                float Cc  = spq + K1;
                float B   = fmaf(242.f, Hpt[k], fmaf(-2.f, pq, K2)); // 2*(121*Spt - Sp*St) + C2*121^2
                float D   = fmaf(121.f, Hpp[k] + Htt[k], K2 - spq);  // 121*(Spp+Stt) - spq + C2*121^2
                acc += __fdividef(A * B, Cc * D);
            }
        }
    }

    // Deterministic block reduction
    red[t] = acc;
    __syncthreads();
    #pragma unroll
    for (int off = NT / 2; off > 0; off >>= 1) {
        if (t < off) red[t] += red[t + off];
        __syncthreads();
    }
    if (t == 0) g_partial[blockIdx.y * NBANDS + blockIdx.x] = red[0];
}

__global__ void __launch_bounds__(256) ssim_final_kernel(float* __restrict__ out)
{
    __shared__ float red[256];
    int t = threadIdx.x;
    float s = g_partial[t] + g_partial[t + 256];
    if (t < NBANDS * NIMG - 512) s += g_partial[t + 512];
    red[t] = s;
    __syncthreads();
    #pragma unroll
    for (int off = 128; off > 0; off >>= 1) {
        if (t < off) red[t] += red[t + off];
        __syncthreads();
    }
    if (t == 0) out[0] = 1.0f - red[0] / NPIX;
}

extern "C" void kernel_launch(void* const* d_in, const int* in_sizes, int n_in,
                              void* d_out, int out_size)
{
    const float* pred = (const float*)d_in[0];
    const float* targ = (const float*)d_in[1];
    dim3 grid(NBANDS, NIMG);
    ssim_band_kernel<<<grid, NT>>>(pred, targ);
    ssim_final_kernel<<<1, 256>>>((float*)d_out);
}

// round 11
// speedup vs baseline: 2.2530x; 1.8669x over previous
#include <cuda_runtime.h>
#include <cuda_bf16.h>

#define IMG_H 512
#define NBANDS 6
#define BANDH 86           // 5*86 + 82 = 512
#define NIMG 96            // 32 batch * 3 channels
#define ROWV4 128          // float4 per row
#define NT 128
#define XSTR 132           // float4 stride per exchange row (2 pad + 128 + 2 pad)
#define ASTR 132           // float stride for aux arrays
#define NBLK (NBANDS * NIMG)   // 576
#define NPIX 25165824.0f

typedef unsigned long long ull;
#define F2FMA(d,a,b,c) asm("fma.rn.f32x2 %0,%1,%2,%3;" : "=l"(d) : "l"(a), "l"(b), "l"(c))
#define F2ADD(d,a,b)   asm("add.rn.f32x2 %0,%1,%2;"    : "=l"(d) : "l"(a), "l"(b))
#define F2MUL(d,a,b)   asm("mul.rn.f32x2 %0,%1,%2;"    : "=l"(d) : "l"(a), "l"(b))
#define F2PACK(d,lo,hi) asm("mov.b64 %0,{%1,%2};" : "=l"(d) : "f"(lo), "f"(hi))
#define F2UNPK(lo,hi,s) asm("mov.b64 {%0,%1},%2;" : "=f"(lo), "=f"(hi) : "l"(s))

__device__ float g_partial[NBLK];
__device__ unsigned int g_count;   // zero-init; last block resets to 0 each launch

__device__ __forceinline__ void horiz5(const float4* __restrict__ buf,
                                       const float* __restrict__ aL,
                                       const float* __restrict__ aF,
                                       int t, float c0, float c1, float c2, float c3,
                                       float H[4])
{
    float  aw = aL[t];          // col 4t-5 (stride-1, conflict-free)
    float4 b  = buf[t + 1];     // cols 4t-4 .. 4t-1
    float4 d  = buf[t + 3];     // cols 4t+4 .. 4t+7
    float  e  = aF[t + 4];      // col 4t+8 (stride-1, conflict-free)
    float h0 = aw + b.x + b.y + b.z + b.w + c0 + c1 + c2 + c3 + d.x + d.y;
    float h1 = h0 - aw  + d.z;
    float h2 = h1 - b.x + d.w;
    float h3 = h2 - b.y + e;
    H[0] = h0; H[1] = h1; H[2] = h2; H[3] = h3;
}

__global__ void __launch_bounds__(NT, 4) ssim_band_kernel(
    const float* __restrict__ pred, const float* __restrict__ targ,
    float* __restrict__ out)
{
    __shared__ float4 xch[2][5 * XSTR];
    __shared__ float  auxL[2][5 * ASTR];   // c3 copies (col 4t+3)
    __shared__ float  auxF[2][5 * ASTR];   // c0 copies (col 4t)
    __shared__ float  red[NT];
    __shared__ int    is_last;

    const int t    = threadIdx.x;
    const int img  = blockIdx.y;
    const int band = blockIdx.x;
    const int r0   = band * BANDH;
    const int h    = (band < NBANDS - 1) ? BANDH : (IMG_H - (NBANDS - 1) * BANDH);
    const int steps = h + 10;

    const float4* __restrict__ P  = (const float4*)pred + (size_t)img * (IMG_H * ROWV4);
    const float4* __restrict__ T4 = (const float4*)targ + (size_t)img * (IMG_H * ROWV4);

    // Zero halo pads: indices {0,1} (threads 0,1) and {130,131} (threads 126,127).
    if (t < 2) {
        #pragma unroll
        for (int b = 0; b < 2; ++b)
            #pragma unroll
            for (int q = 0; q < 5; ++q) {
                xch[b][q * XSTR + t] = make_float4(0.f, 0.f, 0.f, 0.f);
                auxL[b][q * ASTR + t] = 0.f;
                auxF[b][q * ASTR + t] = 0.f;
            }
    } else if (t >= 126) {
        #pragma unroll
        for (int b = 0; b < 2; ++b)
            #pragma unroll
            for (int q = 0; q < 5; ++q) {
                xch[b][q * XSTR + t + 4] = make_float4(0.f, 0.f, 0.f, 0.f);
                auxL[b][q * ASTR + t + 4] = 0.f;
                auxF[b][q * ASTR + t + 4] = 0.f;
            }
    }

    ull vp01=0, vp23=0, vt01=0, vt23=0, vpp01=0, vpp23=0,
        vtt01=0, vtt23=0, vpt01=0, vpt23=0;
    float acc = 0.f;

    ull negone2, two2, ntwo2, c242, c121, K1p, K2p;
    F2PACK(negone2, -1.f, -1.f);
    F2PACK(two2,     2.f,  2.f);
    F2PACK(ntwo2,   -2.f, -2.f);
    F2PACK(c242,   242.f, 242.f);
    F2PACK(c121,   121.f, 121.f);
    F2PACK(K1p, 1.4641f, 1.4641f);      // 0.01^2 * 121^2
    F2PACK(K2p, 13.1769f, 13.1769f);    // 0.03^2 * 121^2

    #pragma unroll 1
    for (int s = 0; s <= steps; ++s) {
        const bool do_load = (s < steps);
        const int iy  = r0 - 5 + s;
        const int iy2 = iy - 11;

        // 1) issue this step's loads early (consumed after part 2)
        float4 p4  = make_float4(0.f,0.f,0.f,0.f);
        float4 q4  = make_float4(0.f,0.f,0.f,0.f);
        float4 po4 = make_float4(0.f,0.f,0.f,0.f);
        float4 qo4 = make_float4(0.f,0.f,0.f,0.f);
        if (do_load && (unsigned)iy < IMG_H) {
            p4 = P[iy * ROWV4 + t];
            q4 = T4[iy * ROWV4 + t];
        }
        if (do_load && s >= 11 && (unsigned)iy2 < IMG_H) {
            po4 = P[iy2 * ROWV4 + t];   // L2-resident (11 rows back)
            qo4 = T4[iy2 * ROWV4 + t];
        }

        // 2) horiz + SSIM for the row published at step s-1 (registers still match)
        if (s >= 11) {
            const float4* buf = xch[(s - 1) & 1];
            const float*  aLb = auxL[(s - 1) & 1];
            const float*  aFb = auxF[(s - 1) & 1];
            float a0, a1, a2, a3;
            float Hp[4], Ht[4], Hpp[4], Htt[4], Hpt[4];
            F2UNPK(a0, a1, vp01);  F2UNPK(a2, a3, vp23);
            horiz5(buf + 0 * XSTR, aLb + 0 * ASTR, aFb + 0 * ASTR, t, a0, a1, a2, a3, Hp);
            F2UNPK(a0, a1, vt01);  F2UNPK(a2, a3, vt23);
            horiz5(buf + 1 * XSTR, aLb + 1 * ASTR, aFb + 1 * ASTR, t, a0, a1, a2, a3, Ht);
            F2UNPK(a0, a1, vpp01); F2UNPK(a2, a3, vpp23);
            horiz5(buf + 2 * XSTR, aLb + 2 * ASTR, aFb + 2 * ASTR, t, a0, a1, a2, a3, Hpp);
            F2UNPK(a0, a1, vtt01); F2UNPK(a2, a3, vtt23);
            horiz5(buf + 3 * XSTR, aLb + 3 * ASTR, aFb + 3 * ASTR, t, a0, a1, a2, a3, Htt);
            F2UNPK(a0, a1, vpt01); F2UNPK(a2, a3, vpt23);
            horiz5(buf + 4 * XSTR, aLb + 4 * ASTR, aFb + 4 * ASTR, t, a0, a1, a2, a3, Hpt);

            float n[4], dn[4];
            #pragma unroll
            for (int j = 0; j < 2; ++j) {
                ull Sp, St, Wpp, Wtt, Wpt;
                F2PACK(Sp,  Hp[2*j],  Hp[2*j+1]);
                F2PACK(St,  Ht[2*j],  Ht[2*j+1]);
                F2PACK(Wpp, Hpp[2*j], Hpp[2*j+1]);
                F2PACK(Wtt, Htt[2*j], Htt[2*j+1]);
                F2PACK(Wpt, Hpt[2*j], Hpt[2*j+1]);
                ull pq, A, spq, tmp, Cc, B, sD, X, D, N, Dd;
                F2MUL(pq, Sp, St);
                F2FMA(A, two2, pq, K1p);           // 2 Sp St + C1*121^2
                F2MUL(tmp, St, St);
                F2FMA(spq, Sp, Sp, tmp);           // Sp^2 + St^2
                F2ADD(Cc, spq, K1p);
                F2FMA(tmp, ntwo2, pq, K2p);
                F2FMA(B, c242, Wpt, tmp);          // 2(121 Spt - Sp St) + C2*121^2
                F2ADD(sD, Wpp, Wtt);
                F2FMA(X, spq, negone2, K2p);
                F2FMA(D, c121, sD, X);             // 121(Spp+Stt) - spq + C2*121^2
                F2MUL(N, A, B);
                F2MUL(Dd, Cc, D);
                F2UNPK(n[2*j],  n[2*j+1],  N);
                F2UNPK(dn[2*j], dn[2*j+1], Dd);
            }
            // one divide per 4 pixels
            float na = fmaf(n[0], dn[1], n[1] * dn[0]);
            float da = dn[0] * dn[1];
            float nb = fmaf(n[2], dn[3], n[3] * dn[2]);
            float db = dn[2] * dn[3];
            float nf = fmaf(na, db, nb * da);
            float df = da * db;
            acc += __fdividef(nf, df);
        }

        // 3) vertical window update (packed)
        if (do_load) {
            ull pn01, pn23, tn01, tn23, po01, po23, to01, to23;
            F2PACK(pn01, p4.x, p4.y);   F2PACK(pn23, p4.z, p4.w);
            F2PACK(tn01, q4.x, q4.y);   F2PACK(tn23, q4.z, q4.w);
            F2PACK(po01, po4.x, po4.y); F2PACK(po23, po4.z, po4.w);
            F2PACK(to01, qo4.x, qo4.y); F2PACK(to23, qo4.z, qo4.w);
            ull npo01, npo23, nto01, nto23;
            F2MUL(npo01, po01, negone2); F2MUL(npo23, po23, negone2);
            F2MUL(nto01, to01, negone2); F2MUL(nto23, to23, negone2);

            F2ADD(vp01, vp01, pn01);   F2ADD(vp01, vp01, npo01);
            F2ADD(vp23, vp23, pn23);   F2ADD(vp23, vp23, npo23);
            F2ADD(vt01, vt01, tn01);   F2ADD(vt01, vt01, nto01);
            F2ADD(vt23, vt23, tn23);   F2ADD(vt23, vt23, nto23);
            F2FMA(vpp01, pn01, pn01, vpp01);  F2FMA(vpp01, npo01, po01, vpp01);
            F2FMA(vpp23, pn23, pn23, vpp23);  F2FMA(vpp23, npo23, po23, vpp23);
            F2FMA(vtt01, tn01, tn01, vtt01);  F2FMA(vtt01, nto01, to01, vtt01);
            F2FMA(vtt23, tn23, tn23, vtt23);  F2FMA(vtt23, nto23, to23, vtt23);
            F2FMA(vpt01, pn01, tn01, vpt01);  F2FMA(vpt01, npo01, to01, vpt01);
            F2FMA(vpt23, pn23, tn23, vpt23);  F2FMA(vpt23, npo23, to23, vpt23);
        }

        // 4) publish updated window sums
        if (s >= 10 && do_load) {
            float4* buf = xch[s & 1];
            float*  aL  = auxL[s & 1];
            float*  aF  = auxF[s & 1];
            float w0, w1, w2, w3;
            F2UNPK(w0, w1, vp01);  F2UNPK(w2, w3, vp23);
            buf[0*XSTR + 2 + t] = make_float4(w0, w1, w2, w3);
            aL[0*ASTR + 2 + t] = w3;  aF[0*ASTR + 2 + t] = w0;
            F2UNPK(w0, w1, vt01);  F2UNPK(w2, w3, vt23);
            buf[1*XSTR + 2 + t] = make_float4(w0, w1, w2, w3);
            aL[1*ASTR + 2 + t] = w3;  aF[1*ASTR + 2 + t] = w0;
            F2UNPK(w0, w1, vpp01); F2UNPK(w2, w3, vpp23);
            buf[2*XSTR + 2 + t] = make_float4(w0, w1, w2, w3);
            aL[2*ASTR + 2 + t] = w3;  aF[2*ASTR + 2 + t] = w0;
            F2UNPK(w0, w1, vtt01); F2UNPK(w2, w3, vtt23);
            buf[3*XSTR + 2 + t] = make_float4(w0, w1, w2, w3);
            aL[3*ASTR + 2 + t] = w3;  aF[3*ASTR + 2 + t] = w0;
            F2UNPK(w0, w1, vpt01); F2UNPK(w2, w3, vpt23);
            buf[4*XSTR + 2 + t] = make_float4(w0, w1, w2, w3);
            aL[4*ASTR + 2 + t] = w3;  aF[4*ASTR + 2 + t] = w0;
        }
        if (s >= 10) __syncthreads();
    }

    // Deterministic block reduction
    red[t] = acc;
    __syncthreads();
    #pragma unroll
    for (int off = NT / 2; off > 0; off >>= 1) {
        if (t < off) red[t] += red[t + off];
        __syncthreads();
    }
    if (t == 0) {
        g_partial[img * NBANDS + band] = red[0];
        __threadfence();
        unsigned v = atomicAdd(&g_count, 1u);
        is_last = (v == NBLK - 1);
    }
    __syncthreads();

    // Last block folds all 576 partials in a fixed order (deterministic).
    if (is_last) {
        float s2 = g_partial[t] + g_partial[t + 128] + g_partial[t + 256] + g_partial[t + 384];
        if (t < NBLK - 512) s2 += g_partial[t + 512];
        red[t] = s2;
        __syncthreads();
        #pragma unroll
        for (int off = NT / 2; off > 0; off >>= 1) {
            if (t < off) red[t] += red[t + off];
            __syncthreads();
        }
        if (t == 0) {
            out[0] = 1.0f - red[0] / NPIX;
            g_count = 0;   // reset for next graph replay
        }
    }
}

extern "C" void kernel_launch(void* const* d_in, const int* in_sizes, int n_in,
                              void* d_out, int out_size)
{
    const float* pred = (const float*)d_in[0];
    const float* targ = (const float*)d_in[1];
    dim3 grid(NBANDS, NIMG);
    ssim_band_kernel<<<grid, NT>>>(pred, targ, (float*)d_out);
}

// round 13
// speedup vs baseline: 2.4607x; 1.0922x over previous
#include <cuda_runtime.h>
#include <cuda_bf16.h>

#define IMG_H 512
#define NBANDS 6
#define BANDH 86           // 5*86 + 82 = 512
#define NIMG 96            // 32 batch * 3 channels
#define ROWV4 128          // float4 per row
#define NT 128
#define XSTR 132           // float4 stride per exchange row (2 pad + 128 + 2 pad)
#define ASTR 132           // float stride for aux arrays
#define NBLK (NBANDS * NIMG)   // 576
#define NPIX 25165824.0f

typedef unsigned long long ull;
#define F2FMA(d,a,b,c) asm("fma.rn.f32x2 %0,%1,%2,%3;" : "=l"(d) : "l"(a), "l"(b), "l"(c))
#define F2ADD(d,a,b)   asm("add.rn.f32x2 %0,%1,%2;"    : "=l"(d) : "l"(a), "l"(b))
#define F2MUL(d,a,b)   asm("mul.rn.f32x2 %0,%1,%2;"    : "=l"(d) : "l"(a), "l"(b))
#define F2PACK(d,lo,hi) asm("mov.b64 %0,{%1,%2};" : "=l"(d) : "f"(lo), "f"(hi))
#define F2UNPK(lo,hi,s) asm("mov.b64 {%0,%1},%2;" : "=f"(lo), "=f"(hi) : "l"(s))

__device__ float g_partial[NBLK];
__device__ unsigned int g_count;   // zero-init; last block resets to 0 each launch

__device__ __forceinline__ void horiz5(const float4* __restrict__ buf,
                                       const float* __restrict__ aL,
                                       const float* __restrict__ aF,
                                       int t, float c0, float c1, float c2, float c3,
                                       float H[4])
{
    float  aw = aL[t];          // col 4t-5 (stride-1, conflict-free)
    float4 b  = buf[t + 1];     // cols 4t-4 .. 4t-1
    float4 d  = buf[t + 3];     // cols 4t+4 .. 4t+7
    float  e  = aF[t + 4];      // col 4t+8 (stride-1, conflict-free)
    float h0 = aw + b.x + b.y + b.z + b.w + c0 + c1 + c2 + c3 + d.x + d.y;
    float h1 = h0 - aw  + d.z;
    float h2 = h1 - b.x + d.w;
    float h3 = h2 - b.y + e;
    H[0] = h0; H[1] = h1; H[2] = h2; H[3] = h3;
}

__global__ void __launch_bounds__(NT, 5) ssim_band_kernel(
    const float* __restrict__ pred, const float* __restrict__ targ,
    float* __restrict__ out)
{
    __shared__ float4 xch[2][4 * XSTR];    // 4 quantities: p, t, p^2+t^2, p*t
    __shared__ float  auxL[2][4 * ASTR];   // c3 copies (col 4t+3)
    __shared__ float  auxF[2][4 * ASTR];   // c0 copies (col 4t)
    __shared__ float  red[NT];
    __shared__ int    is_last;

    const int t    = threadIdx.x;
    const int img  = blockIdx.y;
    const int band = blockIdx.x;
    const int r0   = band * BANDH;
    const int h    = (band < NBANDS - 1) ? BANDH : (IMG_H - (NBANDS - 1) * BANDH);
    const int steps = h + 10;

    const float4* __restrict__ P  = (const float4*)pred + (size_t)img * (IMG_H * ROWV4);
    const float4* __restrict__ T4 = (const float4*)targ + (size_t)img * (IMG_H * ROWV4);

    // Zero halo pads: indices {0,1} (threads 0,1) and {130,131} (threads 126,127).
    if (t < 2) {
        #pragma unroll
        for (int b = 0; b < 2; ++b)
            #pragma unroll
            for (int q = 0; q < 4; ++q) {
                xch[b][q * XSTR + t] = make_float4(0.f, 0.f, 0.f, 0.f);
                auxL[b][q * ASTR + t] = 0.f;
                auxF[b][q * ASTR + t] = 0.f;
            }
    } else if (t >= 126) {
        #pragma unroll
        for (int b = 0; b < 2; ++b)
            #pragma unroll
            for (int q = 0; q < 4; ++q) {
                xch[b][q * XSTR + t + 4] = make_float4(0.f, 0.f, 0.f, 0.f);
                auxL[b][q * ASTR + t + 4] = 0.f;
                auxF[b][q * ASTR + t + 4] = 0.f;
            }
    }

    // 4 packed vertical accumulators x 2 pairs
    ull vp01=0, vp23=0, vt01=0, vt23=0, vss01=0, vss23=0, vpt01=0, vpt23=0;
    float acc = 0.f;

    ull negone2, two2, ntwo2, c242, c121, K1p, K2p;
    F2PACK(negone2, -1.f, -1.f);
    F2PACK(two2,     2.f,  2.f);
    F2PACK(ntwo2,   -2.f, -2.f);
    F2PACK(c242,   242.f, 242.f);
    F2PACK(c121,   121.f, 121.f);
    F2PACK(K1p, 1.4641f, 1.4641f);      // 0.01^2 * 121^2
    F2PACK(K2p, 13.1769f, 13.1769f);    // 0.03^2 * 121^2

    #pragma unroll 1
    for (int s = 0; s <= steps; ++s) {
        const bool do_load = (s < steps);
        const int iy  = r0 - 5 + s;
        const int iy2 = iy - 11;

        // 1) issue this step's loads early (consumed after part 2)
        float4 p4  = make_float4(0.f,0.f,0.f,0.f);
        float4 q4  = make_float4(0.f,0.f,0.f,0.f);
        float4 po4 = make_float4(0.f,0.f,0.f,0.f);
        float4 qo4 = make_float4(0.f,0.f,0.f,0.f);
        if (do_load && (unsigned)iy < IMG_H) {
            p4 = P[iy * ROWV4 + t];
            q4 = T4[iy * ROWV4 + t];
        }
        if (do_load && s >= 11 && (unsigned)iy2 < IMG_H) {
            po4 = P[iy2 * ROWV4 + t];   // L1/L2-resident (11 rows back)
            qo4 = T4[iy2 * ROWV4 + t];
        }

        // 2) horiz + SSIM for the row published at step s-1 (registers still match)
        if (s >= 11) {
            const float4* buf = xch[(s - 1) & 1];
            const float*  aLb = auxL[(s - 1) & 1];
            const float*  aFb = auxF[(s - 1) & 1];
            float a0, a1, a2, a3;
            float Hp[4], Ht[4], Hss[4], Hpt[4];
            F2UNPK(a0, a1, vp01);   F2UNPK(a2, a3, vp23);
            horiz5(buf + 0 * XSTR, aLb + 0 * ASTR, aFb + 0 * ASTR, t, a0, a1, a2, a3, Hp);
            F2UNPK(a0, a1, vt01);   F2UNPK(a2, a3, vt23);
            horiz5(buf + 1 * XSTR, aLb + 1 * ASTR, aFb + 1 * ASTR, t, a0, a1, a2, a3, Ht);
            F2UNPK(a0, a1, vss01);  F2UNPK(a2, a3, vss23);
            horiz5(buf + 2 * XSTR, aLb + 2 * ASTR, aFb + 2 * ASTR, t, a0, a1, a2, a3, Hss);
            F2UNPK(a0, a1, vpt01);  F2UNPK(a2, a3, vpt23);
            horiz5(buf + 3 * XSTR, aLb + 3 * ASTR, aFb + 3 * ASTR, t, a0, a1, a2, a3, Hpt);

            float n[4], dn[4];
            #pragma unroll
            for (int j = 0; j < 2; ++j) {
                ull Sp, St, Wss, Wpt;
                F2PACK(Sp,  Hp[2*j],  Hp[2*j+1]);
                F2PACK(St,  Ht[2*j],  Ht[2*j+1]);
                F2PACK(Wss, Hss[2*j], Hss[2*j+1]);
                F2PACK(Wpt, Hpt[2*j], Hpt[2*j+1]);
                ull pq, A, spq, tmp, Cc, B, X, D, N, Dd;
                F2MUL(pq, Sp, St);
                F2FMA(A, two2, pq, K1p);           // 2 Sp St + C1*121^2
                F2MUL(tmp, St, St);
                F2FMA(spq, Sp, Sp, tmp);           // Sp^2 + St^2
                F2ADD(Cc, spq, K1p);
                F2FMA(tmp, ntwo2, pq, K2p);
                F2FMA(B, c242, Wpt, tmp);          // 2(121 Spt - Sp St) + C2*121^2
                F2FMA(X, spq, negone2, K2p);
                F2FMA(D, c121, Wss, X);            // 121(Spp+Stt) - spq + C2*121^2
                F2MUL(N, A, B);
                F2MUL(Dd, Cc, D);
                F2UNPK(n[2*j],  n[2*j+1],  N);
                F2UNPK(dn[2*j], dn[2*j+1], Dd);
            }
            // one divide per 4 pixels
            float na = fmaf(n[0], dn[1], n[1] * dn[0]);
            float da = dn[0] * dn[1];
            float nb = fmaf(n[2], dn[3], n[3] * dn[2]);
            float db = dn[2] * dn[3];
            float nf = fmaf(na, db, nb * da);
            float df = da * db;
            acc += __fdividef(nf, df);
        }

        // 3) vertical window update (packed): vp, vt, vss = sum(p^2+t^2), vpt
        if (do_load) {
            ull pn01, pn23, tn01, tn23, po01, po23, to01, to23;
            F2PACK(pn01, p4.x, p4.y);   F2PACK(pn23, p4.z, p4.w);
            F2PACK(tn01, q4.x, q4.y);   F2PACK(tn23, q4.z, q4.w);
            F2PACK(po01, po4.x, po4.y); F2PACK(po23, po4.z, po4.w);
            F2PACK(to01, qo4.x, qo4.y); F2PACK(to23, qo4.z, qo4.w);
            ull npo01, npo23, nto01, nto23;
            F2MUL(npo01, po01, negone2); F2MUL(npo23, po23, negone2);
            F2MUL(nto01, to01, negone2); F2MUL(nto23, to23, negone2);

            F2ADD(vp01, vp01, pn01);   F2ADD(vp01, vp01, npo01);
            F2ADD(vp23, vp23, pn23);   F2ADD(vp23, vp23, npo23);
            F2ADD(vt01, vt01, tn01);   F2ADD(vt01, vt01, nto01);
            F2ADD(vt23, vt23, tn23);   F2ADD(vt23, vt23, nto23);
            F2FMA(vss01, pn01, pn01, vss01);  F2FMA(vss01, npo01, po01, vss01);
            F2FMA(vss01, tn01, tn01, vss01);  F2FMA(vss01, nto01, to01, vss01);
            F2FMA(vss23, pn23, pn23, vss23);  F2FMA(vss23, npo23, po23, vss23);
            F2FMA(vss23, tn23, tn23, vss23);  F2FMA(vss23, nto23, to23, vss23);
            F2FMA(vpt01, pn01, tn01, vpt01);  F2FMA(vpt01, npo01, to01, vpt01);
            F2FMA(vpt23, pn23, tn23, vpt23);  F2FMA(vpt23, npo23, to23, vpt23);
        }

        // 4) publish updated window sums
        if (s >= 10 && do_load) {
            float4* buf = xch[s & 1];
            float*  aL  = auxL[s & 1];
            float*  aF  = auxF[s & 1];
            float w0, w1, w2, w3;
            F2UNPK(w0, w1, vp01);   F2UNPK(w2, w3, vp23);
            buf[0*XSTR + 2 + t] = make_float4(w0, w1, w2, w3);
            aL[0*ASTR + 2 + t] = w3;  aF[0*ASTR + 2 + t] = w0;
            F2UNPK(w0, w1, vt01);   F2UNPK(w2, w3, vt23);
            buf[1*XSTR + 2 + t] = make_float4(w0, w1, w2, w3);
            aL[1*ASTR + 2 + t] = w3;  aF[1*ASTR + 2 + t] = w0;
            F2UNPK(w0, w1, vss01);  F2UNPK(w2, w3, vss23);
            buf[2*XSTR + 2 + t] = make_float4(w0, w1, w2, w3);
            aL[2*ASTR + 2 + t] = w3;  aF[2*ASTR + 2 + t] = w0;
            F2UNPK(w0, w1, vpt01);  F2UNPK(w2, w3, vpt23);
            buf[3*XSTR + 2 + t] = make_float4(w0, w1, w2, w3);
            aL[3*ASTR + 2 + t] = w3;  aF[3*ASTR + 2 + t] = w0;
        }
        if (s >= 10) __syncthreads();
    }

    // Deterministic block reduction
    red[t] = acc;
    __syncthreads();
    #pragma unroll
    for (int off = NT / 2; off > 0; off >>= 1) {
        if (t < off) red[t] += red[t + off];
        __syncthreads();
    }
    if (t == 0) {
        g_partial[img * NBANDS + band] = red[0];
        __threadfence();
        unsigned v = atomicAdd(&g_count, 1u);
        is_last = (v == NBLK - 1);
    }
    __syncthreads();

    // Last block folds all 576 partials in a fixed order (deterministic).
    if (is_last) {
        float s2 = g_partial[t] + g_partial[t + 128] + g_partial[t + 256] + g_partial[t + 384];
        if (t < NBLK - 512) s2 += g_partial[t + 512];
        red[t] = s2;
        __syncthreads();
        #pragma unroll
        for (int off = NT / 2; off > 0; off >>= 1) {
            if (t < off) red[t] += red[t + off];
            __syncthreads();
        }
        if (t == 0) {
            out[0] = 1.0f - red[0] / NPIX;
            g_count = 0;   // reset for next graph replay
        }
    }
}

extern "C" void kernel_launch(void* const* d_in, const int* in_sizes, int n_in,
                              void* d_out, int out_size)
{
    const float* pred = (const float*)d_in[0];
    const float* targ = (const float*)d_in[1];
    dim3 grid(NBANDS, NIMG);
    ssim_band_kernel<<<grid, NT>>>(pred, targ, (float*)d_out);
}